// round 15
// baseline (speedup 1.0000x reference)
#include <cuda_runtime.h>

// ---------------------------------------------------------------------------
// IMEX-ETD: CG-solve (I - DT*D*Lap_neumann) x = u, then pointwise ETD update.
// Round 15: round-14 six-kernel graph structure + x2 grid-stride unroll in
// every pass kernel (all loads for two work items issued before arithmetic ->
// doubled per-thread MLP; N4 = 8*PNTH exactly, no remainder).
//   K1: r0 = DT*D*lap(u)            -> m00
//   K2: s0 = A r0                   -> m01, m11
//   K3: t  = A s0                   -> m12, m22
//   K4: v  = A t (registers only)   -> m02, m03, m13, m23
//   K5: 1-block moment sum + 3-step CG trajectory (double) -> c0,c1,c2
//   K6: out = ETD(u + c0 r0 + c1 s0 + c2 t)
// ---------------------------------------------------------------------------

#define N_ELEM   8388608     // 8 * 1 * 1024 * 1024
#define N4       2097152     // float4 count
#define ROW4     256         // float4s per row
#define PBLK     1024
#define PTHR     256
#define PNTH     (PBLK * PTHR)   // N4 / PNTH = 8

#define DT_C     0.1f
#define CG_TAU   0.015

__device__ float g_r0[N_ELEM];
__device__ float g_s0[N_ELEM];
__device__ float g_t [N_ELEM];

// moment partials: 0:m00 1:m01 2:m11 3:m12 4:m22 5:m02 6:m03 7:m13 8:m23
__device__ double g_pm[9][PBLK];
__device__ float  g_c[4];

// ---------------------------------------------------------------------------

__device__ __forceinline__ float dot4f(float4 a, float4 b) {
    return fmaf(a.x, b.x, fmaf(a.y, b.y, fmaf(a.z, b.z, a.w * b.w)));
}

__device__ __forceinline__ float4 lap_mk(float4 c, float4 t, float4 b,
                                         float lf, float rt) {
    float4 L;
    L.x = fmaf(-4.0f, c.x, (lf  + c.y) + (t.x + b.x));
    L.y = fmaf(-4.0f, c.y, (c.x + c.z) + (t.y + b.y));
    L.z = fmaf(-4.0f, c.z, (c.y + c.w) + (t.z + b.z));
    L.w = fmaf(-4.0f, c.w, (c.z + rt ) + (t.w + b.w));
    return L;
}

struct Win { float4 c, t, b; float l, r; };

__device__ __forceinline__ Win load_win(const float* __restrict__ s, int j) {
    Win w;
    int x4 = j & (ROW4 - 1);
    int y  = (j >> 8) & 1023;
    const float4* s4 = (const float4*)s;
    w.c = __ldg(s4 + j);
    w.t = (y > 0)    ? __ldg(s4 + (j - ROW4)) : w.c;
    w.b = (y < 1023) ? __ldg(s4 + (j + ROW4)) : w.c;
    w.l = (x4 > 0)        ? __ldg(s + 4*j - 1) : w.c.x;
    w.r = (x4 < ROW4 - 1) ? __ldg(s + 4*j + 4) : w.c.w;
    return w;
}

// float accumulator in, fixed-order double tree out (thread 0 valid)
__device__ __forceinline__ double block_reduce_f2d(float vf) {
    __shared__ double sh[PTHR / 32];
    double v = (double)vf;
    int lane = threadIdx.x & 31;
    int w    = threadIdx.x >> 5;
#pragma unroll
    for (int o = 16; o; o >>= 1) v += __shfl_down_sync(0xffffffffu, v, o);
    if (lane == 0) sh[w] = v;
    __syncthreads();
    if (w == 0) {
        v = (lane < PTHR / 32) ? sh[lane] : 0.0;
#pragma unroll
        for (int o = 16; o; o >>= 1) v += __shfl_down_sync(0xffffffffu, v, o);
    }
    return v;
}

// A y from a loaded window
__device__ __forceinline__ float4 Aw(Win w, float4 dd) {
    float4 lp = lap_mk(w.c, w.t, w.b, w.l, w.r);
    float4 r;
    r.x = fmaf(-DT_C * dd.x, lp.x, w.c.x);
    r.y = fmaf(-DT_C * dd.y, lp.y, w.c.y);
    r.z = fmaf(-DT_C * dd.z, lp.z, w.c.z);
    r.w = fmaf(-DT_C * dd.w, lp.w, w.c.w);
    return r;
}

// ---------------------------------------------------------------------------
// K1: r0 = DT*D*lap(u); m00   (x2 unroll)

__global__ void __launch_bounds__(PTHR) k_r0(const float* __restrict__ u,
                                             const float* __restrict__ D)
{
    const int tid = blockIdx.x * PTHR + threadIdx.x;
    const float4* __restrict__ D4 = (const float4*)D;
    float4* __restrict__ dst = (float4*)g_r0;
    float a00 = 0.0f;
    for (int j = tid; j < N4; j += 2 * PNTH) {
        int j2 = j + PNTH;
        Win wa = load_win(u, j);
        Win wb = load_win(u, j2);
        float4 dA = __ldg(D4 + j);
        float4 dB = __ldg(D4 + j2);
        float4 la = lap_mk(wa.c, wa.t, wa.b, wa.l, wa.r);
        float4 lb = lap_mk(wb.c, wb.t, wb.b, wb.l, wb.r);
        float4 ra, rb;
        ra.x = DT_C * dA.x * la.x;  ra.y = DT_C * dA.y * la.y;
        ra.z = DT_C * dA.z * la.z;  ra.w = DT_C * dA.w * la.w;
        rb.x = DT_C * dB.x * lb.x;  rb.y = DT_C * dB.y * lb.y;
        rb.z = DT_C * dB.z * lb.z;  rb.w = DT_C * dB.w * lb.w;
        dst[j]  = ra;
        dst[j2] = rb;
        a00 += dot4f(ra, ra) + dot4f(rb, rb);
    }
    double v = block_reduce_f2d(a00);
    if (threadIdx.x == 0) g_pm[0][blockIdx.x] = v;
}

// K2: s0 = A r0; m01, m11   (x2 unroll)
__global__ void __launch_bounds__(PTHR) k_s0(const float* __restrict__ D)
{
    const int tid = blockIdx.x * PTHR + threadIdx.x;
    const float4* __restrict__ D4 = (const float4*)D;
    float4* __restrict__ dst = (float4*)g_s0;
    float a01 = 0.0f, a11 = 0.0f;
    for (int j = tid; j < N4; j += 2 * PNTH) {
        int j2 = j + PNTH;
        Win wa = load_win(g_r0, j);
        Win wb = load_win(g_r0, j2);
        float4 dA = __ldg(D4 + j);
        float4 dB = __ldg(D4 + j2);
        float4 sa = Aw(wa, dA);
        float4 sb = Aw(wb, dB);
        dst[j]  = sa;
        dst[j2] = sb;
        a01 += dot4f(wa.c, sa) + dot4f(wb.c, sb);
        a11 += dot4f(sa, sa)   + dot4f(sb, sb);
    }
    double v0 = block_reduce_f2d(a01);
    __syncthreads();
    double v1 = block_reduce_f2d(a11);
    if (threadIdx.x == 0) {
        g_pm[1][blockIdx.x] = v0;
        g_pm[2][blockIdx.x] = v1;
    }
}

// K3: t = A s0; m12, m22   (x2 unroll)
__global__ void __launch_bounds__(PTHR) k_t(const float* __restrict__ D)
{
    const int tid = blockIdx.x * PTHR + threadIdx.x;
    const float4* __restrict__ D4 = (const float4*)D;
    float4* __restrict__ dst = (float4*)g_t;
    float a12 = 0.0f, a22 = 0.0f;
    for (int j = tid; j < N4; j += 2 * PNTH) {
        int j2 = j + PNTH;
        Win wa = load_win(g_s0, j);
        Win wb = load_win(g_s0, j2);
        float4 dA = __ldg(D4 + j);
        float4 dB = __ldg(D4 + j2);
        float4 ta = Aw(wa, dA);
        float4 tb = Aw(wb, dB);
        dst[j]  = ta;
        dst[j2] = tb;
        a12 += dot4f(wa.c, ta) + dot4f(wb.c, tb);
        a22 += dot4f(ta, ta)   + dot4f(tb, tb);
    }
    double v0 = block_reduce_f2d(a12);
    __syncthreads();
    double v1 = block_reduce_f2d(a22);
    if (threadIdx.x == 0) {
        g_pm[3][blockIdx.x] = v0;
        g_pm[4][blockIdx.x] = v1;
    }
}

// K4: v = A t (registers); m02, m03, m13, m23   (x2 unroll)
__global__ void __launch_bounds__(PTHR) k_v(const float* __restrict__ D)
{
    const int tid = blockIdx.x * PTHR + threadIdx.x;
    const float4* __restrict__ D4 = (const float4*)D;
    const float4* __restrict__ r04 = (const float4*)g_r0;
    const float4* __restrict__ s04 = (const float4*)g_s0;
    float a02 = 0.0f, a03 = 0.0f, a13 = 0.0f, a23 = 0.0f;
    for (int j = tid; j < N4; j += 2 * PNTH) {
        int j2 = j + PNTH;
        Win wa = load_win(g_t, j);
        Win wb = load_win(g_t, j2);
        float4 dA = __ldg(D4 + j);
        float4 dB = __ldg(D4 + j2);
        float4 rA = __ldg(r04 + j);
        float4 rB = __ldg(r04 + j2);
        float4 sA = __ldg(s04 + j);
        float4 sB = __ldg(s04 + j2);
        float4 va = Aw(wa, dA);
        float4 vb = Aw(wb, dB);
        a02 += dot4f(rA, wa.c) + dot4f(rB, wb.c);
        a03 += dot4f(rA, va)   + dot4f(rB, vb);
        a13 += dot4f(sA, va)   + dot4f(sB, vb);
        a23 += dot4f(wa.c, va) + dot4f(wb.c, vb);
    }
    double v0 = block_reduce_f2d(a02);
    __syncthreads();
    double v1 = block_reduce_f2d(a03);
    __syncthreads();
    double v2 = block_reduce_f2d(a13);
    __syncthreads();
    double v3 = block_reduce_f2d(a23);
    if (threadIdx.x == 0) {
        g_pm[5][blockIdx.x] = v0;
        g_pm[6][blockIdx.x] = v1;
        g_pm[7][blockIdx.x] = v2;
        g_pm[8][blockIdx.x] = v3;
    }
}

// ---------------------------------------------------------------------------
// K5 (1 block): sum partials, run 3-step CG trajectory in double.

__global__ void __launch_bounds__(1024) k_coef()
{
    __shared__ double mom[9];
    int lane = threadIdx.x & 31;
    int w    = threadIdx.x >> 5;
    if (w < 9) {
        double s = 0.0;
        for (int j = lane; j < PBLK; j += 32) s += g_pm[w][j];
#pragma unroll
        for (int o = 16; o; o >>= 1) s += __shfl_down_sync(0xffffffffu, s, o);
        if (lane == 0) mom[w] = s;
    }
    __syncthreads();
    if (threadIdx.x == 0) {
        double m00 = mom[0], m01 = mom[1], m11 = mom[2];
        double m12 = mom[3], m22 = mom[4], m02 = mom[5];
        double m03 = mom[6], m13 = mom[7], m23 = mom[8];

        double M[4][4];
        M[0][0] = m00; M[0][1] = m01; M[0][2] = m02; M[0][3] = m03;
        M[1][0] = m01; M[1][1] = m11; M[1][2] = m12; M[1][3] = m13;
        M[2][0] = m02; M[2][1] = m12; M[2][2] = m22; M[2][3] = m23;
        M[3][0] = m03; M[3][1] = m13; M[3][2] = m23; M[3][3] = 0.0;

        double rv[4] = {1.0, 0.0, 0.0, 0.0};
        double pv[4] = {1.0, 0.0, 0.0, 0.0};
        double xv[4] = {0.0, 0.0, 0.0, 0.0};
        double rs = m00;

        for (int step = 0; step < 3; step++) {
            double Apv[4] = {0.0, pv[0], pv[1], pv[2]};
            double pAp = 0.0;
            for (int i = 0; i < 4; i++)
                for (int jq = 0; jq < 4; jq++)
                    pAp += pv[i] * M[i][jq] * Apv[jq];
            float af = (float)(rs / (pAp + 1e-300));
            double ad = (double)af;
            for (int i = 0; i < 4; i++) {
                xv[i] += ad * pv[i];
                rv[i] -= ad * Apv[i];
            }
            if (step == 2) break;
            double rs_new = 0.0;
            for (int i = 0; i < 4; i++)
                for (int jq = 0; jq < 4; jq++)
                    rs_new += rv[i] * M[i][jq] * rv[jq];
            if (rs_new < 0.0) rs_new = 0.0;
            if (sqrt(rs_new) < CG_TAU) break;
            float bf = (float)(rs_new / (rs + 1e-300));
            double bd = (double)bf;
            for (int i = 0; i < 4; i++) pv[i] = rv[i] + bd * pv[i];
            rs = rs_new;
        }
        g_c[0] = (float)xv[0];
        g_c[1] = (float)xv[1];
        g_c[2] = (float)xv[2];
        g_c[3] = 0.0f;
    }
}

// ---------------------------------------------------------------------------
// K6: out = ETD(u + c0 r0 + c1 s0 + c2 t)   (x2 unroll)

__device__ __forceinline__ float4 etd4(float4 ut, float a, float bc,
                                       float e, float em1) {
    float4 un;
    float num = a * ut.x * e;
    float den = fmaf(bc * ut.x, em1, a);
    un.x = (fabsf(den) > 1e-12f) ? (num / den) : ut.x;
    num = a * ut.y * e;
    den = fmaf(bc * ut.y, em1, a);
    un.y = (fabsf(den) > 1e-12f) ? (num / den) : ut.y;
    num = a * ut.z * e;
    den = fmaf(bc * ut.z, em1, a);
    un.z = (fabsf(den) > 1e-12f) ? (num / den) : ut.z;
    num = a * ut.w * e;
    den = fmaf(bc * ut.w, em1, a);
    un.w = (fabsf(den) > 1e-12f) ? (num / den) : ut.w;
    un.x = fminf(fmaxf(un.x, 0.0f), 1.0f);
    un.y = fminf(fmaxf(un.y, 0.0f), 1.0f);
    un.z = fminf(fmaxf(un.z, 0.0f), 1.0f);
    un.w = fminf(fmaxf(un.w, 0.0f), 1.0f);
    return un;
}

__global__ void __launch_bounds__(PTHR) k_etd(const float* __restrict__ u,
                                              const float* __restrict__ kp,
                                              const float* __restrict__ aCp,
                                              const float* __restrict__ Ctp,
                                              float* __restrict__ out)
{
    const int tid = blockIdx.x * PTHR + threadIdx.x;
    float c0 = g_c[0], c1 = g_c[1], c2 = g_c[2];

    float kk = __ldg(&kp[0]);
    float a  = kk - __ldg(&aCp[0]) * __ldg(&Ctp[0]);
    float bc = kk;                               // k / K_CAP, K_CAP = 1
    float adc = fminf(fmaxf(a * DT_C, -60.0f), 60.0f);
    float e   = expf(adc);
    float em1 = e - 1.0f;

    const float4* __restrict__ u4  = (const float4*)u;
    const float4* __restrict__ r04 = (const float4*)g_r0;
    const float4* __restrict__ s04 = (const float4*)g_s0;
    const float4* __restrict__ t4  = (const float4*)g_t;
    float4* __restrict__ o4 = (float4*)out;

    for (int j = tid; j < N4; j += 2 * PNTH) {
        int j2 = j + PNTH;
        float4 uA = __ldg(u4 + j);
        float4 uB = __ldg(u4 + j2);
        float4 rA = __ldg(r04 + j);
        float4 rB = __ldg(r04 + j2);
        float4 sA = __ldg(s04 + j);
        float4 sB = __ldg(s04 + j2);
        float4 tA = __ldg(t4 + j);
        float4 tB = __ldg(t4 + j2);

        float4 xa, xb;
        xa.x = fmaf(c2, tA.x, fmaf(c1, sA.x, fmaf(c0, rA.x, uA.x)));
        xa.y = fmaf(c2, tA.y, fmaf(c1, sA.y, fmaf(c0, rA.y, uA.y)));
        xa.z = fmaf(c2, tA.z, fmaf(c1, sA.z, fmaf(c0, rA.z, uA.z)));
        xa.w = fmaf(c2, tA.w, fmaf(c1, sA.w, fmaf(c0, rA.w, uA.w)));
        xb.x = fmaf(c2, tB.x, fmaf(c1, sB.x, fmaf(c0, rB.x, uB.x)));
        xb.y = fmaf(c2, tB.y, fmaf(c1, sB.y, fmaf(c0, rB.y, uB.y)));
        xb.z = fmaf(c2, tB.z, fmaf(c1, sB.z, fmaf(c0, rB.z, uB.z)));
        xb.w = fmaf(c2, tB.w, fmaf(c1, sB.w, fmaf(c0, rB.w, uB.w)));

        o4[j]  = etd4(xa, a, bc, e, em1);
        o4[j2] = etd4(xb, a, bc, e, em1);
    }
}

// ---------------------------------------------------------------------------

extern "C" void kernel_launch(void* const* d_in, const int* in_sizes, int n_in,
                              void* d_out, int out_size)
{
    const float* u   = (const float*)d_in[0];
    const float* D   = (const float*)d_in[1];
    const float* k   = (const float*)d_in[2];
    const float* aC  = (const float*)d_in[3];
    const float* C_t = (const float*)d_in[4];
    float* out = (float*)d_out;

    k_r0  <<<PBLK, PTHR>>>(u, D);
    k_s0  <<<PBLK, PTHR>>>(D);
    k_t   <<<PBLK, PTHR>>>(D);
    k_v   <<<PBLK, PTHR>>>(D);
    k_coef<<<1, 1024>>>();
    k_etd <<<PBLK, PTHR>>>(u, k, aC, C_t, out);
}

// round 16
// speedup vs baseline: 1.0305x; 1.0305x over previous
#include <cuda_runtime.h>

// ---------------------------------------------------------------------------
// IMEX-ETD: CG-solve (I - DT*D*Lap_neumann) x = u, then pointwise ETD update.
// Round 16: moment-based Krylov CG with ADJOINT-RESTRUCTURED moments.
// The edge-clamped Laplacian L is symmetric, so:
//   m03 = (r0, A t) = m02 - DT*(L(D.r0), t)   <- computed in K3
//   m13 = (s0, A t) = m12 - DT*(L(D.s0), t)   <- computed in K3
//   m23 = (t,  A t) = m22 - DT*sum t.(D.Lt)   <- K4 needs only t-window + D
// Kernels:
//   K1: r0 = DT*D*lap(u)                       -> m00
//   K2: s0 = A r0                              -> m01, m11
//   K3: t  = A s0; L(D.r0), L(D.s0) in regs    -> m12, m22, m02, a03, a13
//   K4: 1 dot: a23 = sum t.(D.Lt)              -> a23
//   K5: 1-block moment assembly + 3-step CG trajectory (double) -> c0,c1,c2
//   K6: out = ETD(u + c0 r0 + c1 s0 + c2 t)
// ~545MB traffic, graph of 6 launches, deterministic fixed-order reductions.
// ---------------------------------------------------------------------------

#define N_ELEM   8388608     // 8 * 1 * 1024 * 1024
#define N4       2097152     // float4 count
#define ROW4     256         // float4s per row
#define PBLK     1024
#define PTHR     256
#define PNTH     (PBLK * PTHR)

#define DT_C     0.1f
#define CG_TAU   0.015

__device__ float g_r0[N_ELEM];
__device__ float g_s0[N_ELEM];
__device__ float g_t [N_ELEM];

// partials: 0:m00 1:m01 2:m11 3:m12 4:m22 5:m02 6:a03 7:a13 8:a23
__device__ double g_pm[9][PBLK];
__device__ float  g_c[4];

// ---------------------------------------------------------------------------

__device__ __forceinline__ float dot4f(float4 a, float4 b) {
    return fmaf(a.x, b.x, fmaf(a.y, b.y, fmaf(a.z, b.z, a.w * b.w)));
}

__device__ __forceinline__ float4 mul4(float4 a, float4 b) {
    float4 r;
    r.x = a.x * b.x; r.y = a.y * b.y; r.z = a.z * b.z; r.w = a.w * b.w;
    return r;
}

__device__ __forceinline__ float4 lap_mk(float4 c, float4 t, float4 b,
                                         float lf, float rt) {
    float4 L;
    L.x = fmaf(-4.0f, c.x, (lf  + c.y) + (t.x + b.x));
    L.y = fmaf(-4.0f, c.y, (c.x + c.z) + (t.y + b.y));
    L.z = fmaf(-4.0f, c.z, (c.y + c.w) + (t.z + b.z));
    L.w = fmaf(-4.0f, c.w, (c.z + rt ) + (t.w + b.w));
    return L;
}

struct Win { float4 c, t, b; float l, r; };

__device__ __forceinline__ Win load_win(const float* __restrict__ s, int j) {
    Win w;
    int x4 = j & (ROW4 - 1);
    int y  = (j >> 8) & 1023;
    const float4* s4 = (const float4*)s;
    w.c = __ldg(s4 + j);
    w.t = (y > 0)    ? __ldg(s4 + (j - ROW4)) : w.c;
    w.b = (y < 1023) ? __ldg(s4 + (j + ROW4)) : w.c;
    w.l = (x4 > 0)        ? __ldg(s + 4*j - 1) : w.c.x;
    w.r = (x4 < ROW4 - 1) ? __ldg(s + 4*j + 4) : w.c.w;
    return w;
}

// float accumulator in, fixed-order double tree out (thread 0 valid)
__device__ __forceinline__ double block_reduce_f2d(float vf) {
    __shared__ double sh[PTHR / 32];
    double v = (double)vf;
    int lane = threadIdx.x & 31;
    int w    = threadIdx.x >> 5;
#pragma unroll
    for (int o = 16; o; o >>= 1) v += __shfl_down_sync(0xffffffffu, v, o);
    if (lane == 0) sh[w] = v;
    __syncthreads();
    if (w == 0) {
        v = (lane < PTHR / 32) ? sh[lane] : 0.0;
#pragma unroll
        for (int o = 16; o; o >>= 1) v += __shfl_down_sync(0xffffffffu, v, o);
    }
    return v;
}

// ---------------------------------------------------------------------------
// K1: r0 = DT*D*lap(u); m00

__global__ void __launch_bounds__(PTHR) k_r0(const float* __restrict__ u,
                                             const float* __restrict__ D)
{
    const int tid = blockIdx.x * PTHR + threadIdx.x;
    const float4* __restrict__ D4 = (const float4*)D;
    float4* __restrict__ dst = (float4*)g_r0;
    float a00 = 0.0f;
    for (int j = tid; j < N4; j += PNTH) {
        Win w = load_win(u, j);
        float4 dd = __ldg(D4 + j);
        float4 lp = lap_mk(w.c, w.t, w.b, w.l, w.r);
        float4 rv;
        rv.x = DT_C * dd.x * lp.x;
        rv.y = DT_C * dd.y * lp.y;
        rv.z = DT_C * dd.z * lp.z;
        rv.w = DT_C * dd.w * lp.w;
        dst[j] = rv;
        a00 += dot4f(rv, rv);
    }
    double v = block_reduce_f2d(a00);
    if (threadIdx.x == 0) g_pm[0][blockIdx.x] = v;
}

// K2: s0 = A r0; m01, m11
__global__ void __launch_bounds__(PTHR) k_s0(const float* __restrict__ D)
{
    const int tid = blockIdx.x * PTHR + threadIdx.x;
    const float4* __restrict__ D4 = (const float4*)D;
    float4* __restrict__ dst = (float4*)g_s0;
    float a01 = 0.0f, a11 = 0.0f;
    for (int j = tid; j < N4; j += PNTH) {
        Win w = load_win(g_r0, j);
        float4 dd = __ldg(D4 + j);
        float4 lp = lap_mk(w.c, w.t, w.b, w.l, w.r);
        float4 sv;
        sv.x = fmaf(-DT_C * dd.x, lp.x, w.c.x);
        sv.y = fmaf(-DT_C * dd.y, lp.y, w.c.y);
        sv.z = fmaf(-DT_C * dd.z, lp.z, w.c.z);
        sv.w = fmaf(-DT_C * dd.w, lp.w, w.c.w);
        dst[j] = sv;
        a01 += dot4f(w.c, sv);
        a11 += dot4f(sv, sv);
    }
    double v0 = block_reduce_f2d(a01);
    __syncthreads();
    double v1 = block_reduce_f2d(a11);
    if (threadIdx.x == 0) {
        g_pm[1][blockIdx.x] = v0;
        g_pm[2][blockIdx.x] = v1;
    }
}

// ---------------------------------------------------------------------------
// K3: t = A s0 (store); adjoint helpers L(D.r0), L(D.s0) in registers;
//     dots m12=(s0,t), m22=(t,t), m02=(r0,t), a03=(L(D.r0),t), a13=(L(D.s0),t)

__global__ void __launch_bounds__(PTHR) k_t_m(const float* __restrict__ D)
{
    const int tid = blockIdx.x * PTHR + threadIdx.x;
    float4* __restrict__ dst = (float4*)g_t;
    float a12 = 0.0f, a22 = 0.0f, a02 = 0.0f, b03 = 0.0f, b13 = 0.0f;

    for (int j = tid; j < N4; j += PNTH) {
        Win wr = load_win(g_r0, j);
        Win ws = load_win(g_s0, j);
        Win wd = load_win(D,    j);

        // t = A s0  (uses D center only)
        float4 ls = lap_mk(ws.c, ws.t, ws.b, ws.l, ws.r);
        float4 tv;
        tv.x = fmaf(-DT_C * wd.c.x, ls.x, ws.c.x);
        tv.y = fmaf(-DT_C * wd.c.y, ls.y, ws.c.y);
        tv.z = fmaf(-DT_C * wd.c.z, ls.z, ws.c.z);
        tv.w = fmaf(-DT_C * wd.c.w, ls.w, ws.c.w);

        // L(D.r0): clamp(q) = clamp(D)*clamp(r0) since both clamp identically
        float4 lqr = lap_mk(mul4(wd.c, wr.c), mul4(wd.t, wr.t),
                            mul4(wd.b, wr.b), wd.l * wr.l, wd.r * wr.r);
        // L(D.s0)
        float4 lqs = lap_mk(mul4(wd.c, ws.c), mul4(wd.t, ws.t),
                            mul4(wd.b, ws.b), wd.l * ws.l, wd.r * ws.r);

        dst[j] = tv;
        a12 += dot4f(ws.c, tv);
        a22 += dot4f(tv, tv);
        a02 += dot4f(wr.c, tv);
        b03 += dot4f(lqr, tv);
        b13 += dot4f(lqs, tv);
    }
    double v0 = block_reduce_f2d(a12);
    __syncthreads();
    double v1 = block_reduce_f2d(a22);
    __syncthreads();
    double v2 = block_reduce_f2d(a02);
    __syncthreads();
    double v3 = block_reduce_f2d(b03);
    __syncthreads();
    double v4 = block_reduce_f2d(b13);
    if (threadIdx.x == 0) {
        g_pm[3][blockIdx.x] = v0;
        g_pm[4][blockIdx.x] = v1;
        g_pm[5][blockIdx.x] = v2;
        g_pm[6][blockIdx.x] = v3;
        g_pm[7][blockIdx.x] = v4;
    }
}

// ---------------------------------------------------------------------------
// K4: a23 = sum t . (D . L t)   (t-window + D center only)

__global__ void __launch_bounds__(PTHR) k_m23(const float* __restrict__ D)
{
    const int tid = blockIdx.x * PTHR + threadIdx.x;
    const float4* __restrict__ D4 = (const float4*)D;
    float a23 = 0.0f;
    for (int j = tid; j < N4; j += PNTH) {
        Win w = load_win(g_t, j);
        float4 dd = __ldg(D4 + j);
        float4 lt = lap_mk(w.c, w.t, w.b, w.l, w.r);
        a23 += dot4f(w.c, mul4(dd, lt));
    }
    double v = block_reduce_f2d(a23);
    if (threadIdx.x == 0) g_pm[8][blockIdx.x] = v;
}

// ---------------------------------------------------------------------------
// K5 (1 block): assemble moments, run 3-step CG trajectory in double.

__global__ void __launch_bounds__(1024) k_coef()
{
    __shared__ double mom[9];
    int lane = threadIdx.x & 31;
    int w    = threadIdx.x >> 5;
    if (w < 9) {
        double s = 0.0;
        for (int j = lane; j < PBLK; j += 32) s += g_pm[w][j];
#pragma unroll
        for (int o = 16; o; o >>= 1) s += __shfl_down_sync(0xffffffffu, s, o);
        if (lane == 0) mom[w] = s;
    }
    __syncthreads();
    if (threadIdx.x == 0) {
        const double DTd = (double)DT_C;
        double m00 = mom[0], m01 = mom[1], m11 = mom[2];
        double m12 = mom[3], m22 = mom[4], m02 = mom[5];
        double m03 = m02 - DTd * mom[6];   // (r0,t) - DT*(L(D.r0), t)
        double m13 = m12 - DTd * mom[7];   // (s0,t) - DT*(L(D.s0), t)
        double m23 = m22 - DTd * mom[8];   // (t,t)  - DT*(t, D.Lt)

        double M[4][4];
        M[0][0] = m00; M[0][1] = m01; M[0][2] = m02; M[0][3] = m03;
        M[1][0] = m01; M[1][1] = m11; M[1][2] = m12; M[1][3] = m13;
        M[2][0] = m02; M[2][1] = m12; M[2][2] = m22; M[2][3] = m23;
        M[3][0] = m03; M[3][1] = m13; M[3][2] = m23; M[3][3] = 0.0;

        double rv[4] = {1.0, 0.0, 0.0, 0.0};
        double pv[4] = {1.0, 0.0, 0.0, 0.0};
        double xv[4] = {0.0, 0.0, 0.0, 0.0};
        double rs = m00;

        for (int step = 0; step < 3; step++) {
            double Apv[4] = {0.0, pv[0], pv[1], pv[2]};
            double pAp = 0.0;
            for (int i = 0; i < 4; i++)
                for (int jq = 0; jq < 4; jq++)
                    pAp += pv[i] * M[i][jq] * Apv[jq];
            float af = (float)(rs / (pAp + 1e-300));
            double ad = (double)af;
            for (int i = 0; i < 4; i++) {
                xv[i] += ad * pv[i];
                rv[i] -= ad * Apv[i];
            }
            if (step == 2) break;
            double rs_new = 0.0;
            for (int i = 0; i < 4; i++)
                for (int jq = 0; jq < 4; jq++)
                    rs_new += rv[i] * M[i][jq] * rv[jq];
            if (rs_new < 0.0) rs_new = 0.0;
            if (sqrt(rs_new) < CG_TAU) break;
            float bf = (float)(rs_new / (rs + 1e-300));
            double bd = (double)bf;
            for (int i = 0; i < 4; i++) pv[i] = rv[i] + bd * pv[i];
            rs = rs_new;
        }
        g_c[0] = (float)xv[0];
        g_c[1] = (float)xv[1];
        g_c[2] = (float)xv[2];
        g_c[3] = 0.0f;
    }
}

// ---------------------------------------------------------------------------
// K6: out = ETD(u + c0 r0 + c1 s0 + c2 t), clipped

__global__ void __launch_bounds__(PTHR) k_etd(const float* __restrict__ u,
                                              const float* __restrict__ kp,
                                              const float* __restrict__ aCp,
                                              const float* __restrict__ Ctp,
                                              float* __restrict__ out)
{
    const int tid = blockIdx.x * PTHR + threadIdx.x;
    float c0 = g_c[0], c1 = g_c[1], c2 = g_c[2];

    float kk = __ldg(&kp[0]);
    float a  = kk - __ldg(&aCp[0]) * __ldg(&Ctp[0]);
    float bc = kk;                               // k / K_CAP, K_CAP = 1
    float adc = fminf(fmaxf(a * DT_C, -60.0f), 60.0f);
    float e   = expf(adc);
    float em1 = e - 1.0f;

    const float4* __restrict__ u4  = (const float4*)u;
    const float4* __restrict__ r04 = (const float4*)g_r0;
    const float4* __restrict__ s04 = (const float4*)g_s0;
    const float4* __restrict__ t4  = (const float4*)g_t;
    float4* __restrict__ o4 = (float4*)out;

    for (int j = tid; j < N4; j += PNTH) {
        float4 uv = __ldg(u4 + j);
        float4 rv = __ldg(r04 + j);
        float4 sv = __ldg(s04 + j);
        float4 tv = __ldg(t4 + j);
        float4 ut;
        ut.x = fmaf(c2, tv.x, fmaf(c1, sv.x, fmaf(c0, rv.x, uv.x)));
        ut.y = fmaf(c2, tv.y, fmaf(c1, sv.y, fmaf(c0, rv.y, uv.y)));
        ut.z = fmaf(c2, tv.z, fmaf(c1, sv.z, fmaf(c0, rv.z, uv.z)));
        ut.w = fmaf(c2, tv.w, fmaf(c1, sv.w, fmaf(c0, rv.w, uv.w)));

        float4 un;
        {
            float num = a * ut.x * e;
            float den = fmaf(bc * ut.x, em1, a);
            un.x = (fabsf(den) > 1e-12f) ? (num / den) : ut.x;
            num = a * ut.y * e;
            den = fmaf(bc * ut.y, em1, a);
            un.y = (fabsf(den) > 1e-12f) ? (num / den) : ut.y;
            num = a * ut.z * e;
            den = fmaf(bc * ut.z, em1, a);
            un.z = (fabsf(den) > 1e-12f) ? (num / den) : ut.z;
            num = a * ut.w * e;
            den = fmaf(bc * ut.w, em1, a);
            un.w = (fabsf(den) > 1e-12f) ? (num / den) : ut.w;
        }
        un.x = fminf(fmaxf(un.x, 0.0f), 1.0f);
        un.y = fminf(fmaxf(un.y, 0.0f), 1.0f);
        un.z = fminf(fmaxf(un.z, 0.0f), 1.0f);
        un.w = fminf(fmaxf(un.w, 0.0f), 1.0f);
        o4[j] = un;
    }
}

// ---------------------------------------------------------------------------

extern "C" void kernel_launch(void* const* d_in, const int* in_sizes, int n_in,
                              void* d_out, int out_size)
{
    const float* u   = (const float*)d_in[0];
    const float* D   = (const float*)d_in[1];
    const float* k   = (const float*)d_in[2];
    const float* aC  = (const float*)d_in[3];
    const float* C_t = (const float*)d_in[4];
    float* out = (float*)d_out;

    k_r0  <<<PBLK, PTHR>>>(u, D);
    k_s0  <<<PBLK, PTHR>>>(D);
    k_t_m <<<PBLK, PTHR>>>(D);
    k_m23 <<<PBLK, PTHR>>>(D);
    k_coef<<<1, 1024>>>();
    k_etd <<<PBLK, PTHR>>>(u, k, aC, C_t, out);
}